// round 3
// baseline (speedup 1.0000x reference)
#include <cuda_runtime.h>
#include <cuda_bf16.h>
#include <cstdint>

#define N_NODES 50000
#define N_EDGES 600000
#define VOCAB   32000
#define D       128

// Scratch: precomputed per-token transformed embeddings
__device__ float g_T1[(size_t)VOCAB * D];   // relu(emb @ w1 + b1) per token
__device__ float g_T2[(size_t)VOCAB * D];   // relu(emb @ w2 + b2) per token

__device__ __forceinline__ uint32_t f32_to_tf32(float x) {
    uint32_t r;
    asm("cvt.rna.tf32.f32 %0, %1;" : "=r"(r) : "f"(x));
    return r;
}

// ---------------------------------------------------------------------------
// TF32 tensor-core GEMM: T = relu(emb @ W + b), blockIdx.y selects table.
// Block tile: 128 rows x 128 cols (full N). 256 threads = 8 warps in 4x2 grid;
// each warp computes 32 rows x 64 cols via m16n8k8 tf32 mma (2 m-tiles x 8 n-tiles).
// K processed in 4 chunks of 32.
// ---------------------------------------------------------------------------
__global__ void __launch_bounds__(256) gemm_tf32_kernel(
    const float* __restrict__ emb,
    const float* __restrict__ w1, const float* __restrict__ b1,
    const float* __restrict__ w2, const float* __restrict__ b2)
{
    const float* W  = blockIdx.y ? w2 : w1;
    const float* Bv = blockIdx.y ? b2 : b1;
    float* outT     = blockIdx.y ? g_T2 : g_T1;

    __shared__ float As[128][36];   // [m][k], tf32 bits; pad 36 -> conflict-free frag loads
    __shared__ float Ws[128][36];   // [n][k] (transposed W), tf32 bits

    const int tid  = threadIdx.x;
    const int warp = tid >> 5;
    const int lane = tid & 31;
    const int g    = lane >> 2;     // groupID 0..7
    const int tg   = lane & 3;      // thread-in-group 0..3

    const int wm   = warp >> 1;     // 0..3 : 32-row strip
    const int wn   = warp & 1;      // 0..1 : 64-col strip
    const int row0 = blockIdx.x * 128;

    float acc[2][8][4];
#pragma unroll
    for (int mt = 0; mt < 2; mt++)
#pragma unroll
        for (int nt = 0; nt < 8; nt++)
#pragma unroll
            for (int i = 0; i < 4; i++) acc[mt][nt][i] = 0.f;

#pragma unroll
    for (int kc = 0; kc < D; kc += 32) {
        // Load A chunk: 128 x 32 fp32 = 1024 float4, 4 per thread; convert to tf32
#pragma unroll
        for (int i = 0; i < 4; i++) {
            int idx = tid + i * 256;          // 0..1023
            int r   = idx >> 3;               // 8 float4 per row
            int c4  = (idx & 7) * 4;
            float4 v = *reinterpret_cast<const float4*>(
                &emb[(size_t)(row0 + r) * D + kc + c4]);
            As[r][c4 + 0] = __uint_as_float(f32_to_tf32(v.x));
            As[r][c4 + 1] = __uint_as_float(f32_to_tf32(v.y));
            As[r][c4 + 2] = __uint_as_float(f32_to_tf32(v.z));
            As[r][c4 + 3] = __uint_as_float(f32_to_tf32(v.w));
        }
        // Load W chunk transposed: W[kc+r][n] -> Ws[n][r]; 32 x 128 = 1024 float4
#pragma unroll
        for (int i = 0; i < 4; i++) {
            int idx = tid + i * 256;
            int r   = idx >> 5;               // 32 float4 per W row
            int c4  = (idx & 31) * 4;
            float4 v = *reinterpret_cast<const float4*>(
                &W[(size_t)(kc + r) * D + c4]);
            Ws[c4 + 0][r] = __uint_as_float(f32_to_tf32(v.x));
            Ws[c4 + 1][r] = __uint_as_float(f32_to_tf32(v.y));
            Ws[c4 + 2][r] = __uint_as_float(f32_to_tf32(v.z));
            Ws[c4 + 3][r] = __uint_as_float(f32_to_tf32(v.w));
        }
        __syncthreads();

#pragma unroll
        for (int k8 = 0; k8 < 4; k8++) {
            const int kb = k8 * 8;
            uint32_t a[2][4];
#pragma unroll
            for (int mt = 0; mt < 2; mt++) {
                int rb = wm * 32 + mt * 16;
                a[mt][0] = __float_as_uint(As[rb + g    ][kb + tg    ]);
                a[mt][1] = __float_as_uint(As[rb + g + 8][kb + tg    ]);
                a[mt][2] = __float_as_uint(As[rb + g    ][kb + tg + 4]);
                a[mt][3] = __float_as_uint(As[rb + g + 8][kb + tg + 4]);
            }
            uint32_t b[8][2];
#pragma unroll
            for (int nt = 0; nt < 8; nt++) {
                int nb = wn * 64 + nt * 8;
                b[nt][0] = __float_as_uint(Ws[nb + g][kb + tg    ]);
                b[nt][1] = __float_as_uint(Ws[nb + g][kb + tg + 4]);
            }
#pragma unroll
            for (int mt = 0; mt < 2; mt++)
#pragma unroll
                for (int nt = 0; nt < 8; nt++) {
                    asm volatile(
                        "mma.sync.aligned.m16n8k8.row.col.f32.tf32.tf32.f32 "
                        "{%0,%1,%2,%3}, {%4,%5,%6,%7}, {%8,%9}, {%0,%1,%2,%3};"
                        : "+f"(acc[mt][nt][0]), "+f"(acc[mt][nt][1]),
                          "+f"(acc[mt][nt][2]), "+f"(acc[mt][nt][3])
                        : "r"(a[mt][0]), "r"(a[mt][1]), "r"(a[mt][2]), "r"(a[mt][3]),
                          "r"(b[nt][0]), "r"(b[nt][1]));
                }
        }
        __syncthreads();
    }

    // Epilogue: +bias, relu, float2 stores
#pragma unroll
    for (int mt = 0; mt < 2; mt++) {
        int r0 = row0 + wm * 32 + mt * 16 + g;
#pragma unroll
        for (int nt = 0; nt < 8; nt++) {
            int col = wn * 64 + nt * 8 + 2 * tg;
            float bx = __ldg(&Bv[col]);
            float by = __ldg(&Bv[col + 1]);
            float2 v0, v1;
            v0.x = fmaxf(acc[mt][nt][0] + bx, 0.f);
            v0.y = fmaxf(acc[mt][nt][1] + by, 0.f);
            v1.x = fmaxf(acc[mt][nt][2] + bx, 0.f);
            v1.y = fmaxf(acc[mt][nt][3] + by, 0.f);
            *reinterpret_cast<float2*>(&outT[(size_t)r0 * D + col])       = v0;
            *reinterpret_cast<float2*>(&outT[(size_t)(r0 + 8) * D + col]) = v1;
        }
    }
}

// ---------------------------------------------------------------------------
// Scatter: one warp per edge, float4 per lane, vector RED to out[dst].
// ---------------------------------------------------------------------------
__global__ void __launch_bounds__(256) scatter_kernel(
    const int* __restrict__ node_tokens,
    const int* __restrict__ edge_tokens,
    const int* __restrict__ src,
    const int* __restrict__ dst,
    float* __restrict__ out)
{
    int e = blockIdx.x * (blockDim.x >> 5) + (threadIdx.x >> 5);
    if (e >= N_EDGES) return;
    int lane = threadIdx.x & 31;

    int s    = __ldg(&src[e]);
    int d    = __ldg(&dst[e]);
    int tok1 = __ldg(&node_tokens[s]);
    int tok2 = __ldg(&edge_tokens[e]);

    const float4 a = *reinterpret_cast<const float4*>(&g_T1[(size_t)tok1 * D + lane * 4]);
    const float4 b = *reinterpret_cast<const float4*>(&g_T2[(size_t)tok2 * D + lane * 4]);

    float4 m;
    m.x = a.x * b.x; m.y = a.y * b.y; m.z = a.z * b.z; m.w = a.w * b.w;

    float* p = out + (size_t)d * D + lane * 4;   // 16B-aligned
    asm volatile("red.relaxed.gpu.global.add.v4.f32 [%0], {%1, %2, %3, %4};"
                 :: "l"(p), "f"(m.x), "f"(m.y), "f"(m.z), "f"(m.w)
                 : "memory");
}

// ---------------------------------------------------------------------------
// Launch
// ---------------------------------------------------------------------------
extern "C" void kernel_launch(void* const* d_in, const int* in_sizes, int n_in,
                              void* d_out, int out_size) {
    const float* emb         = (const float*)d_in[0];
    const float* w1          = (const float*)d_in[1];
    const float* b1          = (const float*)d_in[2];
    const float* w2          = (const float*)d_in[3];
    const float* b2          = (const float*)d_in[4];
    const int*   node_tokens = (const int*)d_in[5];
    const int*   edge_tokens = (const int*)d_in[6];
    const int*   src         = (const int*)d_in[7];
    const int*   dst         = (const int*)d_in[8];
    float*       out         = (float*)d_out;

    // Per-token transformed embeddings: two TF32 GEMMs in one launch
    dim3 ggrid(VOCAB / 128, 2);
    gemm_tf32_kernel<<<ggrid, 256>>>(emb, w1, b1, w2, b2);

    // Zero output (graph-capturable async memset)
    cudaMemsetAsync(out, 0, (size_t)N_NODES * D * sizeof(float));

    // Edge scatter: 1 warp per edge, 8 warps per block
    int nblocks = (N_EDGES + 7) / 8;
    scatter_kernel<<<nblocks, 256>>>(node_tokens, edge_tokens, src, dst, out);
}

// round 4
// speedup vs baseline: 1.5970x; 1.5970x over previous
#include <cuda_runtime.h>
#include <cuda_bf16.h>
#include <cstdint>

#define N_NODES 50000
#define N_EDGES 600000
#define VOCAB   32000
#define D       128

// Scratch: precomputed per-token transformed embeddings
__device__ float g_T1[(size_t)VOCAB * D];   // relu(emb @ w1 + b1) per token
__device__ float g_T2[(size_t)VOCAB * D];   // relu(emb @ w2 + b2) per token

__device__ __forceinline__ uint32_t f32_to_tf32(float x) {
    uint32_t r;
    asm("cvt.rna.tf32.f32 %0, %1;" : "=r"(r) : "f"(x));
    return r;
}

// ---------------------------------------------------------------------------
// Kernel 1: zero the output (harness poisons it to 0xAA)
// ---------------------------------------------------------------------------
__global__ void zero_kernel(float4* __restrict__ out, int n4) {
    int i = blockIdx.x * blockDim.x + threadIdx.x;
    if (i < n4) out[i] = make_float4(0.f, 0.f, 0.f, 0.f);
}

// ---------------------------------------------------------------------------
// TF32 tensor-core GEMM: T = relu(emb @ W + b), blockIdx.y selects table.
// Block tile: 128x128, 8 warps (4x2), each warp 32x64 via m16n8k8 tf32 mma.
// ---------------------------------------------------------------------------
__global__ void __launch_bounds__(256) gemm_tf32_kernel(
    const float* __restrict__ emb,
    const float* __restrict__ w1, const float* __restrict__ b1,
    const float* __restrict__ w2, const float* __restrict__ b2)
{
    const float* W  = blockIdx.y ? w2 : w1;
    const float* Bv = blockIdx.y ? b2 : b1;
    float* outT     = blockIdx.y ? g_T2 : g_T1;

    __shared__ float As[128][36];   // [m][k] tf32 bits, padded
    __shared__ float Ws[128][36];   // [n][k] (transposed W), padded

    const int tid  = threadIdx.x;
    const int warp = tid >> 5;
    const int lane = tid & 31;
    const int g    = lane >> 2;
    const int tg   = lane & 3;

    const int wm   = warp >> 1;
    const int wn   = warp & 1;
    const int row0 = blockIdx.x * 128;

    float acc[2][8][4];
#pragma unroll
    for (int mt = 0; mt < 2; mt++)
#pragma unroll
        for (int nt = 0; nt < 8; nt++)
#pragma unroll
            for (int i = 0; i < 4; i++) acc[mt][nt][i] = 0.f;

#pragma unroll
    for (int kc = 0; kc < D; kc += 32) {
#pragma unroll
        for (int i = 0; i < 4; i++) {
            int idx = tid + i * 256;
            int r   = idx >> 3;
            int c4  = (idx & 7) * 4;
            float4 v = *reinterpret_cast<const float4*>(
                &emb[(size_t)(row0 + r) * D + kc + c4]);
            As[r][c4 + 0] = __uint_as_float(f32_to_tf32(v.x));
            As[r][c4 + 1] = __uint_as_float(f32_to_tf32(v.y));
            As[r][c4 + 2] = __uint_as_float(f32_to_tf32(v.z));
            As[r][c4 + 3] = __uint_as_float(f32_to_tf32(v.w));
        }
#pragma unroll
        for (int i = 0; i < 4; i++) {
            int idx = tid + i * 256;
            int r   = idx >> 5;
            int c4  = (idx & 31) * 4;
            float4 v = *reinterpret_cast<const float4*>(
                &W[(size_t)(kc + r) * D + c4]);
            Ws[c4 + 0][r] = __uint_as_float(f32_to_tf32(v.x));
            Ws[c4 + 1][r] = __uint_as_float(f32_to_tf32(v.y));
            Ws[c4 + 2][r] = __uint_as_float(f32_to_tf32(v.z));
            Ws[c4 + 3][r] = __uint_as_float(f32_to_tf32(v.w));
        }
        __syncthreads();

#pragma unroll
        for (int k8 = 0; k8 < 4; k8++) {
            const int kb = k8 * 8;
            uint32_t a[2][4];
#pragma unroll
            for (int mt = 0; mt < 2; mt++) {
                int rb = wm * 32 + mt * 16;
                a[mt][0] = __float_as_uint(As[rb + g    ][kb + tg    ]);
                a[mt][1] = __float_as_uint(As[rb + g + 8][kb + tg    ]);
                a[mt][2] = __float_as_uint(As[rb + g    ][kb + tg + 4]);
                a[mt][3] = __float_as_uint(As[rb + g + 8][kb + tg + 4]);
            }
            uint32_t b[8][2];
#pragma unroll
            for (int nt = 0; nt < 8; nt++) {
                int nb = wn * 64 + nt * 8;
                b[nt][0] = __float_as_uint(Ws[nb + g][kb + tg    ]);
                b[nt][1] = __float_as_uint(Ws[nb + g][kb + tg + 4]);
            }
#pragma unroll
            for (int mt = 0; mt < 2; mt++)
#pragma unroll
                for (int nt = 0; nt < 8; nt++) {
                    asm volatile(
                        "mma.sync.aligned.m16n8k8.row.col.f32.tf32.tf32.f32 "
                        "{%0,%1,%2,%3}, {%4,%5,%6,%7}, {%8,%9}, {%0,%1,%2,%3};"
                        : "+f"(acc[mt][nt][0]), "+f"(acc[mt][nt][1]),
                          "+f"(acc[mt][nt][2]), "+f"(acc[mt][nt][3])
                        : "r"(a[mt][0]), "r"(a[mt][1]), "r"(a[mt][2]), "r"(a[mt][3]),
                          "r"(b[nt][0]), "r"(b[nt][1]));
                }
        }
        __syncthreads();
    }

#pragma unroll
    for (int mt = 0; mt < 2; mt++) {
        int r0 = row0 + wm * 32 + mt * 16 + g;
#pragma unroll
        for (int nt = 0; nt < 8; nt++) {
            int col = wn * 64 + nt * 8 + 2 * tg;
            float bx = __ldg(&Bv[col]);
            float by = __ldg(&Bv[col + 1]);
            float2 v0, v1;
            v0.x = fmaxf(acc[mt][nt][0] + bx, 0.f);
            v0.y = fmaxf(acc[mt][nt][1] + by, 0.f);
            v1.x = fmaxf(acc[mt][nt][2] + bx, 0.f);
            v1.y = fmaxf(acc[mt][nt][3] + by, 0.f);
            *reinterpret_cast<float2*>(&outT[(size_t)r0 * D + col])       = v0;
            *reinterpret_cast<float2*>(&outT[(size_t)(r0 + 8) * D + col]) = v1;
        }
    }
}

// ---------------------------------------------------------------------------
// Scatter: 4 edges per warp, front-batched loads for MLP.
// Per edge: msg = T1[node_tokens[src[e]]] * T2[edge_tokens[e]]; red.v4 to out[dst[e]].
// 600000 edges = 18750 blocks * 8 warps * 4 edges exactly (no tail).
// ---------------------------------------------------------------------------
#define EPW 4   // edges per warp

__global__ void __launch_bounds__(256) scatter_kernel(
    const int* __restrict__ node_tokens,
    const int* __restrict__ edge_tokens,
    const int* __restrict__ src,
    const int* __restrict__ dst,
    float* __restrict__ out)
{
    const int w    = blockIdx.x * (blockDim.x >> 5) + (threadIdx.x >> 5);
    const int lane = threadIdx.x & 31;
    const int e0   = w * EPW;
    if (e0 >= N_EDGES) return;

    // Batch 1: independent index loads (broadcast across warp)
    int s[EPW], d[EPW], t2[EPW];
#pragma unroll
    for (int i = 0; i < EPW; i++) {
        s[i]  = __ldg(&src[e0 + i]);
        d[i]  = __ldg(&dst[e0 + i]);
        t2[i] = __ldg(&edge_tokens[e0 + i]);
    }
    // Batch 2: dependent token loads (4 independent among themselves)
    int t1[EPW];
#pragma unroll
    for (int i = 0; i < EPW; i++) t1[i] = __ldg(&node_tokens[s[i]]);

    // Batch 3: 8 independent 16B row gathers
    float4 a[EPW], b[EPW];
#pragma unroll
    for (int i = 0; i < EPW; i++) {
        a[i] = *reinterpret_cast<const float4*>(&g_T1[(size_t)t1[i] * D + lane * 4]);
        b[i] = *reinterpret_cast<const float4*>(&g_T2[(size_t)t2[i] * D + lane * 4]);
    }

    // Batch 4: multiply + vector reductions
#pragma unroll
    for (int i = 0; i < EPW; i++) {
        float4 m;
        m.x = a[i].x * b[i].x; m.y = a[i].y * b[i].y;
        m.z = a[i].z * b[i].z; m.w = a[i].w * b[i].w;
        float* p = out + (size_t)d[i] * D + lane * 4;   // 16B-aligned
        asm volatile("red.relaxed.gpu.global.add.v4.f32 [%0], {%1, %2, %3, %4};"
                     :: "l"(p), "f"(m.x), "f"(m.y), "f"(m.z), "f"(m.w)
                     : "memory");
    }
}

// ---------------------------------------------------------------------------
// Launch
// ---------------------------------------------------------------------------
extern "C" void kernel_launch(void* const* d_in, const int* in_sizes, int n_in,
                              void* d_out, int out_size) {
    const float* emb         = (const float*)d_in[0];
    const float* w1          = (const float*)d_in[1];
    const float* b1          = (const float*)d_in[2];
    const float* w2          = (const float*)d_in[3];
    const float* b2          = (const float*)d_in[4];
    const int*   node_tokens = (const int*)d_in[5];
    const int*   edge_tokens = (const int*)d_in[6];
    const int*   src         = (const int*)d_in[7];
    const int*   dst         = (const int*)d_in[8];
    float*       out         = (float*)d_out;

    // Zero output with a kernel (NOT legacy-stream memset — capture-safe & overlappable)
    int n4 = N_NODES * D / 4;
    zero_kernel<<<(n4 + 255) / 256, 256>>>((float4*)out, n4);

    // Per-token transformed embeddings: two TF32 GEMMs in one launch
    dim3 ggrid(VOCAB / 128, 2);
    gemm_tf32_kernel<<<ggrid, 256>>>(emb, w1, b1, w2, b2);

    // Edge scatter: 4 edges per warp, 8 warps per block
    int warps = (N_EDGES + EPW - 1) / EPW;
    int nblocks = (warps + 7) / 8;
    scatter_kernel<<<nblocks, 256>>>(node_tokens, edge_tokens, src, dst, out);
}

// round 7
// speedup vs baseline: 1.8356x; 1.1494x over previous
#include <cuda_runtime.h>
#include <cuda_fp16.h>
#include <cuda_bf16.h>
#include <cstdint>

#define N_NODES 50000
#define N_EDGES 600000
#define VOCAB   32000
#define D       128

// Scratch: precomputed per-token transformed embeddings, fp16 storage
// (halves scatter gather traffic; both tables = 16.4 MB, L2-resident)
__device__ __half g_T1h[(size_t)VOCAB * D];   // relu(emb @ w1 + b1) per token
__device__ __half g_T2h[(size_t)VOCAB * D];   // relu(emb @ w2 + b2) per token

__device__ __forceinline__ uint32_t f32_to_tf32(float x) {
    uint32_t r;
    asm("cvt.rna.tf32.f32 %0, %1;" : "=r"(r) : "f"(x));
    return r;
}

// ---------------------------------------------------------------------------
// Kernel 1: zero the output (harness poisons it to 0xAA)
// ---------------------------------------------------------------------------
__global__ void zero_kernel(float4* __restrict__ out, int n4) {
    int i = blockIdx.x * blockDim.x + threadIdx.x;
    if (i < n4) out[i] = make_float4(0.f, 0.f, 0.f, 0.f);
}

// ---------------------------------------------------------------------------
// TF32 tensor-core GEMM: T = relu(emb @ W + b) -> fp16 table.
// Block tile 128x128, 8 warps (4x2), warp tile 32x64 via m16n8k8 tf32 mma.
// ---------------------------------------------------------------------------
__global__ void __launch_bounds__(256) gemm_tf32_kernel(
    const float* __restrict__ emb,
    const float* __restrict__ w1, const float* __restrict__ b1,
    const float* __restrict__ w2, const float* __restrict__ b2)
{
    const float* W   = blockIdx.y ? w2 : w1;
    const float* Bv  = blockIdx.y ? b2 : b1;
    __half* outT     = blockIdx.y ? g_T2h : g_T1h;

    __shared__ float As[128][36];   // [m][k] tf32 bits, padded (conflict-free frags)
    __shared__ float Ws[128][36];   // [n][k] (transposed W), padded

    const int tid  = threadIdx.x;
    const int warp = tid >> 5;
    const int lane = tid & 31;
    const int g    = lane >> 2;
    const int tg   = lane & 3;

    const int wm   = warp >> 1;
    const int wn   = warp & 1;
    const int row0 = blockIdx.x * 128;

    float acc[2][8][4];
#pragma unroll
    for (int mt = 0; mt < 2; mt++)
#pragma unroll
        for (int nt = 0; nt < 8; nt++)
#pragma unroll
            for (int i = 0; i < 4; i++) acc[mt][nt][i] = 0.f;

#pragma unroll
    for (int kc = 0; kc < D; kc += 32) {
#pragma unroll
        for (int i = 0; i < 4; i++) {
            int idx = tid + i * 256;
            int r   = idx >> 3;
            int c4  = (idx & 7) * 4;
            float4 v = *reinterpret_cast<const float4*>(
                &emb[(size_t)(row0 + r) * D + kc + c4]);
            As[r][c4 + 0] = __uint_as_float(f32_to_tf32(v.x));
            As[r][c4 + 1] = __uint_as_float(f32_to_tf32(v.y));
            As[r][c4 + 2] = __uint_as_float(f32_to_tf32(v.z));
            As[r][c4 + 3] = __uint_as_float(f32_to_tf32(v.w));
        }
#pragma unroll
        for (int i = 0; i < 4; i++) {
            int idx = tid + i * 256;
            int r   = idx >> 5;
            int c4  = (idx & 31) * 4;
            float4 v = *reinterpret_cast<const float4*>(
                &W[(size_t)(kc + r) * D + c4]);
            Ws[c4 + 0][r] = __uint_as_float(f32_to_tf32(v.x));
            Ws[c4 + 1][r] = __uint_as_float(f32_to_tf32(v.y));
            Ws[c4 + 2][r] = __uint_as_float(f32_to_tf32(v.z));
            Ws[c4 + 3][r] = __uint_as_float(f32_to_tf32(v.w));
        }
        __syncthreads();

#pragma unroll
        for (int k8 = 0; k8 < 4; k8++) {
            const int kb = k8 * 8;
            uint32_t a[2][4];
#pragma unroll
            for (int mt = 0; mt < 2; mt++) {
                int rb = wm * 32 + mt * 16;
                a[mt][0] = __float_as_uint(As[rb + g    ][kb + tg    ]);
                a[mt][1] = __float_as_uint(As[rb + g + 8][kb + tg    ]);
                a[mt][2] = __float_as_uint(As[rb + g    ][kb + tg + 4]);
                a[mt][3] = __float_as_uint(As[rb + g + 8][kb + tg + 4]);
            }
            uint32_t b[8][2];
#pragma unroll
            for (int nt = 0; nt < 8; nt++) {
                int nb = wn * 64 + nt * 8;
                b[nt][0] = __float_as_uint(Ws[nb + g][kb + tg    ]);
                b[nt][1] = __float_as_uint(Ws[nb + g][kb + tg + 4]);
            }
#pragma unroll
            for (int mt = 0; mt < 2; mt++)
#pragma unroll
                for (int nt = 0; nt < 8; nt++) {
                    asm volatile(
                        "mma.sync.aligned.m16n8k8.row.col.f32.tf32.tf32.f32 "
                        "{%0,%1,%2,%3}, {%4,%5,%6,%7}, {%8,%9}, {%0,%1,%2,%3};"
                        : "+f"(acc[mt][nt][0]), "+f"(acc[mt][nt][1]),
                          "+f"(acc[mt][nt][2]), "+f"(acc[mt][nt][3])
                        : "r"(a[mt][0]), "r"(a[mt][1]), "r"(a[mt][2]), "r"(a[mt][3]),
                          "r"(b[nt][0]), "r"(b[nt][1]));
                }
        }
        __syncthreads();
    }

    // Epilogue: +bias, relu, fp16 convert, half2 stores
#pragma unroll
    for (int mt = 0; mt < 2; mt++) {
        int r0 = row0 + wm * 32 + mt * 16 + g;
#pragma unroll
        for (int nt = 0; nt < 8; nt++) {
            int col = wn * 64 + nt * 8 + 2 * tg;
            float bx = __ldg(&Bv[col]);
            float by = __ldg(&Bv[col + 1]);
            __half2 h0 = __floats2half2_rn(fmaxf(acc[mt][nt][0] + bx, 0.f),
                                           fmaxf(acc[mt][nt][1] + by, 0.f));
            __half2 h1 = __floats2half2_rn(fmaxf(acc[mt][nt][2] + bx, 0.f),
                                           fmaxf(acc[mt][nt][3] + by, 0.f));
            *reinterpret_cast<__half2*>(&outT[(size_t)r0 * D + col])       = h0;
            *reinterpret_cast<__half2*>(&outT[(size_t)(r0 + 8) * D + col]) = h1;
        }
    }
}

// ---------------------------------------------------------------------------
// Scatter: 8 edges per warp, front-batched loads (16 outstanding row gathers).
// fp16 gathers, fp32 multiply, fp32 vector RED to out[dst].
// 600000 edges = 9375 blocks * 8 warps * 8 edges exactly (no tail).
// ---------------------------------------------------------------------------
#define EPW 8   // edges per warp

__global__ void __launch_bounds__(256) scatter_kernel(
    const int* __restrict__ node_tokens,
    const int* __restrict__ edge_tokens,
    const int* __restrict__ src,
    const int* __restrict__ dst,
    float* __restrict__ out)
{
    const int w    = blockIdx.x * (blockDim.x >> 5) + (threadIdx.x >> 5);
    const int lane = threadIdx.x & 31;
    const int e0   = w * EPW;
    if (e0 >= N_EDGES) return;

    // Batch 1: independent index loads
    int s[EPW], d[EPW], t2[EPW];
#pragma unroll
    for (int i = 0; i < EPW; i++) {
        s[i]  = __ldg(&src[e0 + i]);
        d[i]  = __ldg(&dst[e0 + i]);
        t2[i] = __ldg(&edge_tokens[e0 + i]);
    }
    // Batch 2: dependent token loads (8 independent among themselves)
    int t1[EPW];
#pragma unroll
    for (int i = 0; i < EPW; i++) t1[i] = __ldg(&node_tokens[s[i]]);

    // Batch 3: 16 independent 8B row gathers (lane covers cols 4*lane..4*lane+3)
    uint2 ah[EPW], bh[EPW];
#pragma unroll
    for (int i = 0; i < EPW; i++) {
        ah[i] = *reinterpret_cast<const uint2*>(&g_T1h[(size_t)t1[i] * D + lane * 4]);
        bh[i] = *reinterpret_cast<const uint2*>(&g_T2h[(size_t)t2[i] * D + lane * 4]);
    }

    // Batch 4: fp32 multiply + vector reductions
#pragma unroll
    for (int i = 0; i < EPW; i++) {
        float2 a0 = __half22float2(*reinterpret_cast<const __half2*>(&ah[i].x));
        float2 a1 = __half22float2(*reinterpret_cast<const __half2*>(&ah[i].y));
        float2 b0 = __half22float2(*reinterpret_cast<const __half2*>(&bh[i].x));
        float2 b1 = __half22float2(*reinterpret_cast<const __half2*>(&bh[i].y));
        float m0 = a0.x * b0.x;
        float m1 = a0.y * b0.y;
        float m2 = a1.x * b1.x;
        float m3 = a1.y * b1.y;
        float* p = out + (size_t)d[i] * D + lane * 4;   // 16B-aligned
        asm volatile("red.global.add.v4.f32 [%0], {%1, %2, %3, %4};"
                     :: "l"(p), "f"(m0), "f"(m1), "f"(m2), "f"(m3)
                     : "memory");
    }
}

// ---------------------------------------------------------------------------
// Launch
// ---------------------------------------------------------------------------
extern "C" void kernel_launch(void* const* d_in, const int* in_sizes, int n_in,
                              void* d_out, int out_size) {
    const float* emb         = (const float*)d_in[0];
    const float* w1          = (const float*)d_in[1];
    const float* b1          = (const float*)d_in[2];
    const float* w2          = (const float*)d_in[3];
    const float* b2          = (const float*)d_in[4];
    const int*   node_tokens = (const int*)d_in[5];
    const int*   edge_tokens = (const int*)d_in[6];
    const int*   src         = (const int*)d_in[7];
    const int*   dst         = (const int*)d_in[8];
    float*       out         = (float*)d_out;

    // Zero output
    int n4 = N_NODES * D / 4;
    zero_kernel<<<(n4 + 255) / 256, 256>>>((float4*)out, n4);

    // Per-token transformed embeddings: two TF32 GEMMs in one launch
    dim3 ggrid(VOCAB / 128, 2);
    gemm_tf32_kernel<<<ggrid, 256>>>(emb, w1, b1, w2, b2);

    // Edge scatter: 8 edges per warp, 8 warps per block
    int warps = (N_EDGES + EPW - 1) / EPW;
    int nblocks = (warps + 7) / 8;
    scatter_kernel<<<nblocks, 256>>>(node_tokens, edge_tokens, src, dst, out);
}